// round 13
// baseline (speedup 1.0000x reference)
#include <cuda_runtime.h>
#include <cstdint>

// Problem constants
#define NB    4
#define NN    262144
#define NBUCK 1024
#define KSEL  6000
#define CAP   8192
#define PROP  1000
#define NMS_THR 0.7f
#define MROW64 96          // u64 words per mask row (6144 bits >= 6000)
#define NWORDS ((KSEL + 63) / 64)   // 94

typedef unsigned long long u64;

// ---------------- device scratch (no allocations allowed) ----------------
__device__ int    g_hist[NB][NBUCK];
__device__ int    g_bcnt[NB][NBUCK];
__device__ int    g_base[NB][NBUCK];
__device__ int    g_bstar[NB];
__device__ u64    g_keys[NB][CAP];
__device__ float4 g_boxes[NB][KSEL];
__device__ u64    g_mask[NB][KSEL][MROW64];   // ~18.4 MB, L2-resident

// ---------------- kernel Z: zero scratch ----------------
__global__ void k_zero() {
    int t = blockIdx.x * blockDim.x + threadIdx.x;
    int total = NB * NBUCK;
    for (int p = t; p < total; p += gridDim.x * blockDim.x) {
        ((int*)g_hist)[p] = 0;
        ((int*)g_bcnt)[p] = 0;
    }
}

// ---------------- kernel A: per-batch histogram of fg scores ----------------
// grid (128, NB) x 256; each thread loads 4 float4 = 8 score pairs (LDG.128)
__global__ void k_hist(const float4* __restrict__ scores4) {
    __shared__ int sh[NBUCK];
    int t = threadIdx.x;
    int b = blockIdx.y;
    for (int p = t; p < NBUCK; p += 256) sh[p] = 0;
    __syncthreads();
    int base = blockIdx.x * 1024;                      // in float4 units
    const float4* sp = scores4 + (size_t)b * (NN / 2);
    #pragma unroll
    for (int r = 0; r < 4; ++r) {
        float4 v = sp[base + r * 256 + t];             // elems 2f (.x,.y), 2f+1 (.z,.w)
        int bk0 = (int)(v.y * 1024.0f);
        int bk1 = (int)(v.w * 1024.0f);
        bk0 = min(max(bk0, 0), NBUCK - 1);
        bk1 = min(max(bk1, 0), NBUCK - 1);
        atomicAdd(&sh[bk0], 1);
        atomicAdd(&sh[bk1], 1);
    }
    __syncthreads();
    for (int p = t; p < NBUCK; p += 256)
        if (sh[p]) atomicAdd(&g_hist[b][p], sh[p]);
}

// ---------------- kernel B: suffix-sum, threshold bucket + bucket bases -------
__global__ void k_findthr() {
    __shared__ int s[NBUCK];
    int b = blockIdx.x, t = threadIdx.x;
    int h = g_hist[b][t];
    s[t] = h;
    __syncthreads();
    for (int off = 1; off < NBUCK; off <<= 1) {
        int v = (t + off < NBUCK) ? s[t + off] : 0;
        __syncthreads();
        s[t] += v;
        __syncthreads();
    }
    g_base[b][t] = s[t] - h;      // elements in strictly-higher buckets
    if (s[t] >= KSEL && (t == NBUCK - 1 || s[t + 1] < KSEL))
        g_bstar[b] = t;
}

// ---------------- kernel C: bucket-ordered scatter of candidates -------------
// grid (128, NB) x 256, same vectorized load pattern as k_hist
__global__ void k_compact(const float4* __restrict__ scores4) {
    int t = threadIdx.x;
    int b = blockIdx.y;
    int bstar = g_bstar[b];
    int base = blockIdx.x * 1024;
    const float4* sp = scores4 + (size_t)b * (NN / 2);
    #pragma unroll
    for (int r = 0; r < 4; ++r) {
        int f = base + r * 256 + t;
        float4 v = sp[f];
        #pragma unroll
        for (int half = 0; half < 2; ++half) {
            float s = half ? v.w : v.y;
            int   i = 2 * f + half;
            int bk = (int)(s * 1024.0f);
            bk = min(max(bk, 0), NBUCK - 1);
            if (bk >= bstar) {
                int pos = g_base[b][bk] + atomicAdd(&g_bcnt[b][bk], 1);
                if (pos < CAP) {
                    unsigned sb = __float_as_uint(s);   // s >= 0 -> monotonic
                    g_keys[b][pos] = ((u64)sb << 32) | (0xFFFFFFFFu - (unsigned)i);
                }
            }
        }
    }
}

// ---------------- kernel D: per-bucket segment sort (desc), ~256 elems each ---
// grid (NBUCK, NB) x 256 threads; bucket-major-desc + in-bucket key-desc == global order
__global__ void k_bsort() {
    __shared__ u64 sk[1024];
    int bk = blockIdx.x, b = blockIdx.y, t = threadIdx.x;
    if (bk < g_bstar[b]) return;
    int n = g_bcnt[b][bk];
    if (n <= 0) return;
    if (n > 1024) n = 1024;                // statistically impossible; safety clamp
    int base = g_base[b][bk];
    if (base >= KSEL) return;              // segment entirely past top-6000: never read
    for (int p = t; p < 1024; p += 256)
        sk[p] = (p < n) ? g_keys[b][base + p] : 0ULL;
    __syncthreads();
    for (int k = 2; k <= 1024; k <<= 1) {
        for (int j = k >> 1; j > 0; j >>= 1) {
            for (int i = t; i < 1024; i += 256) {
                int ixj = i ^ j;
                if (ixj > i) {
                    u64 a = sk[i], c = sk[ixj];
                    bool desc = ((i & k) == 0);
                    if (desc ? (a < c) : (a > c)) { sk[i] = c; sk[ixj] = a; }
                }
            }
            __syncthreads();
        }
    }
    for (int p = t; p < n; p += 256)
        g_keys[b][base + p] = sk[p];
}

// ---------------- kernel E: gather + apply box deltas + clip ----------------
__global__ void k_boxes(const float4* __restrict__ deltas,
                        const float4* __restrict__ anchors) {
    int gid = blockIdx.x * blockDim.x + threadIdx.x;
    if (gid >= NB * KSEL) return;
    int b = gid / KSEL;
    int r = gid - b * KSEL;
    int j = (int)(0xFFFFFFFFu - (unsigned)(g_keys[b][r] & 0xFFFFFFFFull));
    float4 a = anchors[(size_t)b * NN + j];
    float4 d = deltas[(size_t)b * NN + j];
    float dx = d.x * 0.1f, dy = d.y * 0.1f, dw = d.z * 0.2f, dh = d.w * 0.2f;
    float w  = a.z - a.x;
    float h  = a.w - a.y;
    float cx = a.x + 0.5f * w;
    float cy = a.y + 0.5f * h;
    cx = cx + dx * w;
    cy = cy + dy * h;
    w  = w * expf(dw);
    h  = h * expf(dh);
    float x0 = cx - 0.5f * w, y0 = cy - 0.5f * h;
    float x1 = cx + 0.5f * w, y1 = cy + 0.5f * h;
    x0 = fminf(fmaxf(x0, 0.0f), 1.0f);
    y0 = fminf(fmaxf(y0, 0.0f), 1.0f);
    x1 = fminf(fmaxf(x1, 0.0f), 1.0f);
    y1 = fminf(fmaxf(y1, 0.0f), 1.0f);
    g_boxes[b][r] = make_float4(x0, y0, x1, y1);
}

// ---------------- kernel F: pairwise suppression bitmask ----------------
// grid (24, 94, NB) x 256 threads. Tile: 64 rows x 256 cols.
// Bit (i, j) set iff j > i and IoU(box_i, box_j) > 0.7 (bit-exact vs fdiv test).
__global__ void k_mask() {
    int b  = blockIdx.z;
    int ir = blockIdx.y * 64;
    int jc = blockIdx.x * 256;
    if (jc + 256 <= ir) return;     // all pairs strictly j < i: bits never read
    __shared__ float4 srow[64];
    __shared__ float  sarea[64];
    int t = threadIdx.x;
    if (t < 64) {
        int i = ir + t;
        float4 bx = (i < KSEL) ? g_boxes[b][i] : make_float4(0.f, 0.f, 0.f, 0.f);
        srow[t]  = bx;
        sarea[t] = __fmul_rn(bx.z - bx.x, bx.w - bx.y);
    }
    int j = jc + t;
    float4 cb = (j < KSEL) ? g_boxes[b][j] : make_float4(0.f, 0.f, 0.f, 0.f);
    float  ca = __fmul_rn(cb.z - cb.x, cb.w - cb.y);
    __syncthreads();

    int lane = t & 31, warp = t >> 5;
    unsigned* mask32 = (unsigned*)&g_mask[b][0][0];
    int nrows = KSEL - ir; if (nrows > 64) nrows = 64;
    for (int r = 0; r < nrows; ++r) {
        int i = ir + r;
        float4 rb = srow[r];
        float  ra = sarea[r];
        bool p = false;
        if (j > i && j < KSEL) {
            float ltx = fmaxf(rb.x, cb.x);
            float lty = fmaxf(rb.y, cb.y);
            float rbx = fminf(rb.z, cb.z);
            float rby = fminf(rb.w, cb.w);
            float wx = fmaxf(rbx - ltx, 0.0f);
            float wy = fmaxf(rby - lty, 0.0f);
            float inter = __fmul_rn(wx, wy);
            // exact reference order: ((a_i + a_j) - inter) + 1e-12
            float denom = ((ra + ca) - inter) + 1e-12f;
            float lim = __fmul_rn(NMS_THR, denom);
            if      (inter > lim * 1.00001f) p = true;        // safely above
            else if (inter < lim * 0.99999f) p = false;       // safely below
            else    p = (__fdiv_rn(inter, denom) > NMS_THR);  // exact, rare
        }
        unsigned bal = __ballot_sync(0xFFFFFFFFu, p);
        if (lane == 0)
            mask32[(size_t)i * (2 * MROW64) + (jc >> 5) + warp] = bal;
    }
}

// ---------------- kernel G: word-chunked greedy scan, 1 warp/batch ------------
__global__ void __launch_bounds__(32, 1) k_scan(float* __restrict__ out) {
    __shared__ int sidx[PROP];
    int b = blockIdx.x, lane = threadIdx.x;
    float4* outB = (float4*)(out + (size_t)b * PROP * 4);
    for (int p = lane; p < PROP; p += 32)
        outB[p] = make_float4(0.f, 0.f, 0.f, 0.f);

    u64 r0 = 0, r1 = 0, r2 = 0;     // remv bits: words lane, lane+32, lane+64
    int kept = 0;
    for (int w = 0; w < NWORDS && kept < PROP; ++w) {
        int slot = w >> 5;          // uniform across warp
        u64 v = (slot == 0) ? r0 : ((slot == 1) ? r1 : r2);
        u64 cur = __shfl_sync(0xFFFFFFFFu, v, w & 31);
        u64 lim = (w == NWORDS - 1 && (KSEL & 63))
                    ? ((1ULL << (KSEL & 63)) - 1) : ~0ULL;
        u64 avail = ~cur & lim;     // surviving candidates in this word

        // prefetch rows of the first 4 candidates (6 x 128B lines each)
        {
            u64 a = avail;
            int c0 = a ? __ffsll(a) - 1 : -1; a &= a - 1;
            int c1 = a ? __ffsll(a) - 1 : -1; a &= a - 1;
            int c2 = a ? __ffsll(a) - 1 : -1; a &= a - 1;
            int c3 = a ? __ffsll(a) - 1 : -1;
            int which = lane / 6;
            int cc = (which == 0) ? c0 : (which == 1) ? c1 : (which == 2) ? c2 : c3;
            if (lane < 24 && cc >= 0) {
                const char* pf = (const char*)&g_mask[b][w * 64 + cc][0] + (lane % 6) * 128;
                asm volatile("prefetch.global.L1 [%0];" :: "l"(pf));
            }
        }

        while (avail) {
            int bit = __ffsll(avail) - 1;
            int i = w * 64 + bit;
            if (lane == 0) sidx[kept] = i;
            ++kept;
            if (kept >= PROP) break;
            const u64* row = &g_mask[b][i][0];
            u64 m0 = row[lane];
            u64 m1 = row[lane + 32];
            u64 m2 = row[lane + 64];
            r0 |= m0; r1 |= m1; r2 |= m2;
            // refresh current word with this row's suppressions
            u64 mv = (slot == 0) ? m0 : ((slot == 1) ? m1 : m2);
            u64 rw = __shfl_sync(0xFFFFFFFFu, mv, w & 31);
            avail &= ~rw;
            avail &= ~(1ULL << bit);
            // prefetch the next two surviving candidates' rows
            u64 a2 = avail;
            int n0 = a2 ? __ffsll(a2) - 1 : -1; a2 &= a2 - 1;
            int n1 = a2 ? __ffsll(a2) - 1 : -1;
            int cc = (lane < 6) ? n0 : n1;
            if (lane < 12 && cc >= 0) {
                const char* pf = (const char*)&g_mask[b][w * 64 + cc][0] + (lane % 6) * 128;
                asm volatile("prefetch.global.L1 [%0];" :: "l"(pf));
            }
        }
    }
    __syncwarp();
    for (int p = lane; p < kept; p += 32)
        outB[p] = g_boxes[b][sidx[p]];
}

// ---------------- launch ----------------
extern "C" void kernel_launch(void* const* d_in, const int* in_sizes, int n_in,
                              void* d_out, int out_size) {
    const float4* scores4 = (const float4*)d_in[0];  // (4,262144,2) as float4
    const float4* deltas  = (const float4*)d_in[1];  // (4,262144,4)
    const float4* anchors = (const float4*)d_in[2];  // (4,262144,4)
    float* out = (float*)d_out;                      // (4,1000,4)

    k_zero<<<8, 512>>>();
    k_hist<<<dim3(128, NB), 256>>>(scores4);
    k_findthr<<<NB, NBUCK>>>();
    k_compact<<<dim3(128, NB), 256>>>(scores4);
    k_bsort<<<dim3(NBUCK, NB), 256>>>();
    k_boxes<<<(NB * KSEL + 255) / 256, 256>>>(deltas, anchors);
    k_mask<<<dim3(24, 94, NB), 256>>>();
    k_scan<<<NB, 32>>>(out);
}

// round 14
// speedup vs baseline: 1.7227x; 1.7227x over previous
#include <cuda_runtime.h>
#include <cstdint>

// Problem constants
#define NB    4
#define NN    262144
#define NBUCK 1024
#define KSEL  6000
#define CAP   8192
#define PROP  1000
#define NMS_THR 0.7f
#define MROW64 96                   // u64 words per mask row (6144 bits >= 6000)
#define NWORDS ((KSEL + 63) / 64)   // 94

typedef unsigned long long u64;

// dynamic smem for k_scan: double row buffer + remv + kept list
// buf: 2 * 64 * MROW64 u64 = 98304 B ; remv: 96 u64 ; sidx: PROP int ; ctrl
#define SCAN_SMEM_BYTES (2 * 64 * MROW64 * 8 + MROW64 * 8 + PROP * 4 + 64)

// ---------------- device scratch (no allocations allowed) ----------------
__device__ int    g_hist[NB][NBUCK];
__device__ int    g_bcnt[NB][NBUCK];
__device__ int    g_base[NB][NBUCK];
__device__ int    g_bstar[NB];
__device__ u64    g_keys[NB][CAP];
__device__ float4 g_boxes[NB][KSEL];
__device__ u64    g_mask[NB][KSEL][MROW64];   // ~18.4 MB, L2-resident

// ---------------- kernel Z: zero scratch ----------------
__global__ void k_zero() {
    int t = blockIdx.x * blockDim.x + threadIdx.x;
    int total = NB * NBUCK;
    for (int p = t; p < total; p += gridDim.x * blockDim.x) {
        ((int*)g_hist)[p] = 0;
        ((int*)g_bcnt)[p] = 0;
    }
}

// ---------------- kernel A: per-batch histogram of fg scores ----------------
// grid (128, NB) x 256; each thread loads 4 float4 = 8 score pairs (LDG.128)
__global__ void k_hist(const float4* __restrict__ scores4) {
    __shared__ int sh[NBUCK];
    int t = threadIdx.x;
    int b = blockIdx.y;
    for (int p = t; p < NBUCK; p += 256) sh[p] = 0;
    __syncthreads();
    int base = blockIdx.x * 1024;                      // in float4 units
    const float4* sp = scores4 + (size_t)b * (NN / 2);
    #pragma unroll
    for (int r = 0; r < 4; ++r) {
        float4 v = sp[base + r * 256 + t];             // elems 2f (.x,.y), 2f+1 (.z,.w)
        int bk0 = (int)(v.y * 1024.0f);
        int bk1 = (int)(v.w * 1024.0f);
        bk0 = min(max(bk0, 0), NBUCK - 1);
        bk1 = min(max(bk1, 0), NBUCK - 1);
        atomicAdd(&sh[bk0], 1);
        atomicAdd(&sh[bk1], 1);
    }
    __syncthreads();
    for (int p = t; p < NBUCK; p += 256)
        if (sh[p]) atomicAdd(&g_hist[b][p], sh[p]);
}

// ---------------- kernel B: suffix-sum, threshold bucket + bucket bases -------
__global__ void k_findthr() {
    __shared__ int s[NBUCK];
    int b = blockIdx.x, t = threadIdx.x;
    int h = g_hist[b][t];
    s[t] = h;
    __syncthreads();
    for (int off = 1; off < NBUCK; off <<= 1) {
        int v = (t + off < NBUCK) ? s[t + off] : 0;
        __syncthreads();
        s[t] += v;
        __syncthreads();
    }
    g_base[b][t] = s[t] - h;      // elements in strictly-higher buckets
    if (s[t] >= KSEL && (t == NBUCK - 1 || s[t + 1] < KSEL))
        g_bstar[b] = t;
}

// ---------------- kernel C: bucket-ordered scatter of candidates -------------
// grid (128, NB) x 256, same vectorized load pattern as k_hist
__global__ void k_compact(const float4* __restrict__ scores4) {
    int t = threadIdx.x;
    int b = blockIdx.y;
    int bstar = g_bstar[b];
    int base = blockIdx.x * 1024;
    const float4* sp = scores4 + (size_t)b * (NN / 2);
    #pragma unroll
    for (int r = 0; r < 4; ++r) {
        int f = base + r * 256 + t;
        float4 v = sp[f];
        #pragma unroll
        for (int half = 0; half < 2; ++half) {
            float s = half ? v.w : v.y;
            int   i = 2 * f + half;
            int bk = (int)(s * 1024.0f);
            bk = min(max(bk, 0), NBUCK - 1);
            if (bk >= bstar) {
                int pos = g_base[b][bk] + atomicAdd(&g_bcnt[b][bk], 1);
                if (pos < CAP) {
                    unsigned sb = __float_as_uint(s);   // s >= 0 -> monotonic
                    g_keys[b][pos] = ((u64)sb << 32) | (0xFFFFFFFFu - (unsigned)i);
                }
            }
        }
    }
}

// ---------------- kernel D: per-bucket segment sort (desc), ~256 elems each ---
// grid (NBUCK, NB) x 256 threads; bucket-major-desc + in-bucket key-desc == global order
__global__ void k_bsort() {
    __shared__ u64 sk[1024];
    int bk = blockIdx.x, b = blockIdx.y, t = threadIdx.x;
    if (bk < g_bstar[b]) return;
    int n = g_bcnt[b][bk];
    if (n <= 0) return;
    if (n > 1024) n = 1024;                // statistically impossible; safety clamp
    int base = g_base[b][bk];
    if (base >= KSEL) return;              // segment entirely past top-6000: never read
    for (int p = t; p < 1024; p += 256)
        sk[p] = (p < n) ? g_keys[b][base + p] : 0ULL;
    __syncthreads();
    for (int k = 2; k <= 1024; k <<= 1) {
        for (int j = k >> 1; j > 0; j >>= 1) {
            for (int i = t; i < 1024; i += 256) {
                int ixj = i ^ j;
                if (ixj > i) {
                    u64 a = sk[i], c = sk[ixj];
                    bool desc = ((i & k) == 0);
                    if (desc ? (a < c) : (a > c)) { sk[i] = c; sk[ixj] = a; }
                }
            }
            __syncthreads();
        }
    }
    for (int p = t; p < n; p += 256)
        g_keys[b][base + p] = sk[p];
}

// ---------------- kernel E: gather + apply box deltas + clip ----------------
__global__ void k_boxes(const float4* __restrict__ deltas,
                        const float4* __restrict__ anchors) {
    int gid = blockIdx.x * blockDim.x + threadIdx.x;
    if (gid >= NB * KSEL) return;
    int b = gid / KSEL;
    int r = gid - b * KSEL;
    int j = (int)(0xFFFFFFFFu - (unsigned)(g_keys[b][r] & 0xFFFFFFFFull));
    float4 a = anchors[(size_t)b * NN + j];
    float4 d = deltas[(size_t)b * NN + j];
    float dx = d.x * 0.1f, dy = d.y * 0.1f, dw = d.z * 0.2f, dh = d.w * 0.2f;
    float w  = a.z - a.x;
    float h  = a.w - a.y;
    float cx = a.x + 0.5f * w;
    float cy = a.y + 0.5f * h;
    cx = cx + dx * w;
    cy = cy + dy * h;
    w  = w * expf(dw);
    h  = h * expf(dh);
    float x0 = cx - 0.5f * w, y0 = cy - 0.5f * h;
    float x1 = cx + 0.5f * w, y1 = cy + 0.5f * h;
    x0 = fminf(fmaxf(x0, 0.0f), 1.0f);
    y0 = fminf(fmaxf(y0, 0.0f), 1.0f);
    x1 = fminf(fmaxf(x1, 0.0f), 1.0f);
    y1 = fminf(fmaxf(y1, 0.0f), 1.0f);
    g_boxes[b][r] = make_float4(x0, y0, x1, y1);
}

// ---------------- kernel F: pairwise suppression bitmask ----------------
// grid (24, 94, NB) x 256 threads. Tile: 64 rows x 256 cols.
// Bit (i, j) set iff j > i and IoU(box_i, box_j) > 0.7 (bit-exact vs fdiv test).
__global__ void k_mask() {
    int b  = blockIdx.z;
    int ir = blockIdx.y * 64;
    int jc = blockIdx.x * 256;
    if (jc + 256 <= ir) return;     // all pairs strictly j < i: bits never read
    __shared__ float4 srow[64];
    __shared__ float  sarea[64];
    int t = threadIdx.x;
    if (t < 64) {
        int i = ir + t;
        float4 bx = (i < KSEL) ? g_boxes[b][i] : make_float4(0.f, 0.f, 0.f, 0.f);
        srow[t]  = bx;
        sarea[t] = __fmul_rn(bx.z - bx.x, bx.w - bx.y);
    }
    int j = jc + t;
    float4 cb = (j < KSEL) ? g_boxes[b][j] : make_float4(0.f, 0.f, 0.f, 0.f);
    float  ca = __fmul_rn(cb.z - cb.x, cb.w - cb.y);
    __syncthreads();

    int lane = t & 31, warp = t >> 5;
    unsigned* mask32 = (unsigned*)&g_mask[b][0][0];
    int nrows = KSEL - ir; if (nrows > 64) nrows = 64;
    for (int r = 0; r < nrows; ++r) {
        int i = ir + r;
        float4 rb = srow[r];
        float  ra = sarea[r];
        bool p = false;
        if (j > i && j < KSEL) {
            float ltx = fmaxf(rb.x, cb.x);
            float lty = fmaxf(rb.y, cb.y);
            float rbx = fminf(rb.z, cb.z);
            float rby = fminf(rb.w, cb.w);
            float wx = fmaxf(rbx - ltx, 0.0f);
            float wy = fmaxf(rby - lty, 0.0f);
            float inter = __fmul_rn(wx, wy);
            // exact reference order: ((a_i + a_j) - inter) + 1e-12
            float denom = ((ra + ca) - inter) + 1e-12f;
            float lim = __fmul_rn(NMS_THR, denom);
            if      (inter > lim * 1.00001f) p = true;        // safely above
            else if (inter < lim * 0.99999f) p = false;       // safely below
            else    p = (__fdiv_rn(inter, denom) > NMS_THR);  // exact, rare
        }
        unsigned bal = __ballot_sync(0xFFFFFFFFu, p);
        if (lane == 0)
            mask32[(size_t)i * (2 * MROW64) + (jc >> 5) + warp] = bal;
    }
}

// ---------------- kernel G: pipelined smem-staged greedy scan -----------------
// 1 block x 1024 threads per batch. Double-buffered staging of 64 mask rows
// (48 KB) per word; serial resolve touches only SMEM (LDS ~29 cyc per kept).
__global__ void __launch_bounds__(1024, 1) k_scan(float* __restrict__ out) {
    extern __shared__ u64 smem[];
    u64* buf  = smem;                          // [2][64][MROW64]
    u64* remv = smem + 2 * 64 * MROW64;        // [MROW64]
    int* sidx = (int*)(remv + MROW64);         // [PROP]
    volatile int* ctrl = (int*)(sidx + PROP);  // [0]=kept, [1]=keptmask lo, [2]=hi, [3]=done

    int b = blockIdx.x, t = threadIdx.x;
    float4* outB = (float4*)(out + (size_t)b * PROP * 4);
    for (int p = t; p < PROP; p += 1024)
        outB[p] = make_float4(0.f, 0.f, 0.f, 0.f);
    for (int p = t; p < MROW64; p += 1024)
        remv[p] = 0ULL;
    if (t < 4) ((int*)ctrl)[t] = 0;

    // preload word 0 rows: 64 rows x MROW64 u64 = 6144 u64, 6 per thread
    {
        const u64* src = &g_mask[b][0][0];
        #pragma unroll
        for (int q = 0; q < 6; ++q) {
            int p = q * 1024 + t;              // p < 6144
            buf[p] = src[p];
        }
    }
    __syncthreads();

    for (int w = 0; w < NWORDS; ++w) {
        int cb_ = w & 1;
        // issue prefetch of word w+1 rows into the other buffer (drained by the
        // end-of-iteration barrier; latency overlapped with resolve + OR below)
        if (w + 1 < NWORDS) {
            const u64* src = &g_mask[b][(w + 1) * 64][0];
            u64* dst = buf + (cb_ ^ 1) * 64 * MROW64;
            #pragma unroll
            for (int q = 0; q < 6; ++q) {
                int p = q * 1024 + t;
                dst[p] = src[p];
            }
        }
        // serial resolve of word w (thread 0 only; smem-only chain)
        if (t == 0) {
            const u64* rows = buf + cb_ * 64 * MROW64;
            u64 lim = (w == NWORDS - 1 && (KSEL & 63))
                        ? ((1ULL << (KSEL & 63)) - 1) : ~0ULL;
            u64 avail = ~remv[w] & lim;
            u64 keptmask = 0;
            int kept = ctrl[0];
            while (avail) {
                int bit = __ffsll(avail) - 1;
                sidx[kept++] = w * 64 + bit;
                keptmask |= (1ULL << bit);
                if (kept >= PROP) { ctrl[3] = 1; break; }
                avail &= ~rows[(size_t)bit * MROW64 + w];
                avail &= ~(1ULL << bit);
            }
            ctrl[0] = kept;
            ((int*)ctrl)[1] = (int)(keptmask & 0xFFFFFFFFu);
            ((int*)ctrl)[2] = (int)(keptmask >> 32);
        }
        __syncthreads();
        if (ctrl[3]) break;
        // parallel OR of kept rows into remv (only words > w matter; full row harmless)
        u64 keptmask = ((u64)(unsigned)((int*)ctrl)[2] << 32) |
                        (u64)(unsigned)((int*)ctrl)[1];
        if (keptmask) {
            const u64* rows = buf + cb_ * 64 * MROW64;
            int wordid = t & (MROW64 | (MROW64 - 1));   // not used; see below
            // distribute: thread handles (row r, word p) pairs
            int nk = __popcll(keptmask);
            // flatten kept rows into iteration: for each kept bit, 96 words
            for (int x = t; x < nk * MROW64; x += 1024) {
                int kr = x / MROW64;
                int p  = x - kr * MROW64;
                // find kr-th set bit of keptmask
                u64 m = keptmask;
                for (int z = 0; z < kr; ++z) m &= m - 1;
                int bit = __ffsll(m) - 1;
                atomicOr((unsigned long long*)&remv[p],
                         rows[(size_t)bit * MROW64 + p]);
            }
        }
        __syncthreads();
    }

    __syncthreads();
    int kept = ctrl[0];
    if (kept > PROP) kept = PROP;
    for (int p = t; p < kept; p += 1024)
        outB[p] = g_boxes[b][sidx[p]];
}

// ---------------- launch ----------------
extern "C" void kernel_launch(void* const* d_in, const int* in_sizes, int n_in,
                              void* d_out, int out_size) {
    const float4* scores4 = (const float4*)d_in[0];  // (4,262144,2) as float4
    const float4* deltas  = (const float4*)d_in[1];  // (4,262144,4)
    const float4* anchors = (const float4*)d_in[2];  // (4,262144,4)
    float* out = (float*)d_out;                      // (4,1000,4)

    cudaFuncSetAttribute(k_scan, cudaFuncAttributeMaxDynamicSharedMemorySize,
                         SCAN_SMEM_BYTES);

    k_zero<<<8, 512>>>();
    k_hist<<<dim3(128, NB), 256>>>(scores4);
    k_findthr<<<NB, NBUCK>>>();
    k_compact<<<dim3(128, NB), 256>>>(scores4);
    k_bsort<<<dim3(NBUCK, NB), 256>>>();
    k_boxes<<<(NB * KSEL + 255) / 256, 256>>>(deltas, anchors);
    k_mask<<<dim3(24, 94, NB), 256>>>();
    k_scan<<<NB, 1024, SCAN_SMEM_BYTES>>>(out);
}